// round 6
// baseline (speedup 1.0000x reference)
#include <cuda_runtime.h>
#include <cuda_bf16.h>
#include <math.h>

#define NA 8400
#define BSZ 32
#define NM 32
#define NC 80
#define TOPK 9

__device__ unsigned int g_maskpos[BSZ * NA];
__device__ float2       g_ac[NA];               // anchor centers

// Zero score region (float4-coalesced), zero gt bitmask, compute centers.
__global__ __launch_bounds__(256) void k_prep(
    const float* __restrict__ anc, float4* __restrict__ scr4)
{
    const int i = blockIdx.x * blockDim.x + threadIdx.x;
    const int NS4 = BSZ * NA * NC / 4;          // 5,376,000
    if (i < NS4) scr4[i] = make_float4(0.f, 0.f, 0.f, 0.f);
    if (i < BSZ * NA / 4) ((uint4*)g_maskpos)[i] = make_uint4(0u, 0u, 0u, 0u);
    if (i < NA) {
        const float4 ab = ((const float4*)anc)[i];
        g_ac[i] = make_float2((ab.x + ab.z) * 0.5f, (ab.y + ab.w) * 0.5f);
    }
}

__device__ __forceinline__ unsigned long long u64min(unsigned long long a, unsigned long long b) {
    return a < b ? a : b;
}
__device__ __forceinline__ unsigned long long u64max(unsigned long long a, unsigned long long b) {
    return a < b ? b : a;
}

// One BLOCK (128 thr = 4 warps) per (b,g) pair. Selection by SQUARED distance
// (monotone with sqrt -> identical top-9 set, no sqrt.rn sequences).
__global__ __launch_bounds__(128) void k_pairs(
    const float* __restrict__ anc,
    const float* __restrict__ gtb,
    const float* __restrict__ mask_gt)
{
    __shared__ unsigned long long s_keys[3][36];
    __shared__ int s_cand[27];

    const int tid  = threadIdx.x;
    const int lane = tid & 31;
    const int wq   = tid >> 5;                  // 0..3

    const int p = blockIdx.x;
    const int b = p >> 5;
    const int g = p & 31;
    if (mask_gt[p] <= 0.0f) return;             // block-uniform -> barriers safe

    const float4 gt = ((const float4*)gtb)[p];
    const float gx = (gt.x + gt.z) * 0.5f;
    const float gy = (gt.y + gt.w) * 0.5f;

    const int starts[3] = {0, 6400, 8000};
    const int lens[3]   = {6400, 1600, 400};

    for (int lvl = 0; lvl < 3; ++lvl) {
        unsigned long long kk[TOPK];
        #pragma unroll
        for (int j = 0; j < TOPK; ++j) kk[j] = 0xFFFFFFFFFFFFFFFFull;

        const int start = starts[lvl], L = lens[lvl];

        // This warp's slice: elements == wq*32+lane (mod 128); 8-way batched.
        for (int base = wq * 32; base < L; base += 1024) {
            float cx[8], cy[8];
            #pragma unroll
            for (int j = 0; j < 8; ++j) {
                const int al = base + j * 128 + lane;
                float2 c = make_float2(3.0e18f, 3.0e18f);   // d2 -> inf, sorts last
                if (al < L) c = g_ac[start + al];
                cx[j] = c.x; cy[j] = c.y;
            }
            #pragma unroll
            for (int j = 0; j < 8; ++j) {
                const int al = base + j * 128 + lane;
                const float dx = gx - cx[j], dy = gy - cy[j];
                const float d2 = fmaf(dx, dx, dy * dy);     // squared distance
                const unsigned long long key =
                    ((unsigned long long)__float_as_uint(d2) << 32) |
                    (unsigned int)(start + al);
                if (key < kk[TOPK - 1]) {
                    // branchless sorted insert (select chain, predicable)
                    unsigned long long x = key;
                    #pragma unroll
                    for (int q = 0; q < TOPK; ++q) {
                        const unsigned long long lo = u64min(kk[q], x);
                        x = u64max(kk[q], x);
                        kk[q] = lo;
                    }
                }
            }
        }

        // Per-warp top-9 extraction: 9 rounds of warp-wide u64 min + pop.
        #pragma unroll
        for (int r = 0; r < TOPK; ++r) {
            const unsigned long long v = kk[0];
            unsigned long long m = v;
            #pragma unroll
            for (int s = 16; s > 0; s >>= 1) {
                const unsigned long long o = __shfl_xor_sync(0xffffffffu, m, s);
                if (o < m) m = o;
            }
            if (v == m) {                        // idx bits make keys unique
                #pragma unroll
                for (int j = 0; j < TOPK - 1; ++j) kk[j] = kk[j + 1];
                kk[TOPK - 1] = 0xFFFFFFFFFFFFFFFFull;
            }
            if (lane == 0) s_keys[lvl][wq * TOPK + r] = m;
        }
    }
    __syncthreads();

    // Warp 0: rank-select top-9 of each level's 36 keys (order irrelevant
    // downstream: mean/std threshold + membership only).
    if (wq == 0) {
        for (int lvl = 0; lvl < 3; ++lvl) {
            #pragma unroll
            for (int half = 0; half < 2; ++half) {
                const int i = lane + half * 32;
                if (i < 36) {
                    const unsigned long long my = s_keys[lvl][i];
                    int rank = 0;
                    #pragma unroll
                    for (int j = 0; j < 36; ++j)
                        rank += (s_keys[lvl][j] < my) ? 1 : 0;
                    if (rank < TOPK)
                        s_cand[lvl * TOPK + rank] = (int)(unsigned int)my;
                }
            }
        }
        __syncwarp();

        // Candidate overlaps (_iou2d: unclipped areas, union eps 1e-6)
        float ov = 0.0f;
        int ca = 0;
        float4 ab = make_float4(0.f, 0.f, 0.f, 0.f);
        if (lane < 27) {
            ca = s_cand[lane];
            ab = ((const float4*)anc)[ca];
            const float area1 = (gt.z - gt.x) * (gt.w - gt.y);
            const float area2 = (ab.z - ab.x) * (ab.w - ab.y);
            const float ltx = fmaxf(gt.x, ab.x), lty = fmaxf(gt.y, ab.y);
            const float rbx = fminf(gt.z, ab.z), rby = fminf(gt.w, ab.w);
            const float ww = fmaxf(rbx - ltx, 0.0f), hh = fmaxf(rby - lty, 0.0f);
            const float o = ww * hh;
            ov = o / fmaxf(area1 + area2 - o, 1e-6f);
        }

        // mean + std(ddof=1) threshold via warp sums
        float s = (lane < 27) ? ov : 0.0f;
        #pragma unroll
        for (int sft = 16; sft > 0; sft >>= 1) s += __shfl_xor_sync(0xffffffffu, s, sft);
        const float mean = s * (1.0f / 27.0f);
        float dv = (lane < 27) ? (ov - mean) * (ov - mean) : 0.0f;
        #pragma unroll
        for (int sft = 16; sft > 0; sft >>= 1) dv += __shfl_xor_sync(0xffffffffu, dv, sft);
        const float thr = mean + sqrtf(dv * (1.0f / 26.0f));

        if (lane < 27 && ov > thr) {
            const float ax = (ab.x + ab.z) * 0.5f;
            const float ay = (ab.y + ab.w) * 0.5f;
            const float mn = fminf(fminf(ax - gt.x, ay - gt.y),
                                   fminf(gt.z - ax, gt.w - ay));
            if (mn > 1e-9f) atomicOr(&g_maskpos[b * NA + ca], 1u << g);
        }
    }
}

// One thread per (b, anchor): resolve multi-assignment, write outputs.
__global__ __launch_bounds__(256) void k_assign(
    const float* __restrict__ anc,
    const int*   __restrict__ gt_labels,
    const float* __restrict__ gtb,
    const float* __restrict__ pd,
    float* __restrict__ o_lab,
    float* __restrict__ o_box,
    float* __restrict__ o_scr,
    float* __restrict__ o_fg)
{
    const int idx = blockIdx.x * blockDim.x + threadIdx.x;
    if (idx >= BSZ * NA) return;
    const int b = idx / NA;
    const int a = idx - b * NA;

    const unsigned int m = g_maskpos[idx];
    const int cnt = __popc(m);
    int tgt = 0;
    const bool fg = (cnt > 0);

    if (cnt == 1) {
        tgt = __ffs(m) - 1;
    } else if (cnt > 1) {
        // argmax over gts of full overlaps (first-occurrence ties)
        const float4 ab = ((const float4*)anc)[a];
        const float area2 = (ab.z - ab.x) * (ab.w - ab.y);
        float best = -1.0f;
        for (int gg = 0; gg < NM; ++gg) {
            const float4 gb = ((const float4*)gtb)[b * NM + gg];
            const float area1 = (gb.z - gb.x) * (gb.w - gb.y);
            const float ltx = fmaxf(gb.x, ab.x), lty = fmaxf(gb.y, ab.y);
            const float rbx = fminf(gb.z, ab.z), rby = fminf(gb.w, ab.w);
            const float ww = fmaxf(rbx - ltx, 0.0f), hh = fmaxf(rby - lty, 0.0f);
            const float ovv = ww * hh;
            const float v = ovv / fmaxf(area1 + area2 - ovv, 1e-6f);
            if (v > best) { best = v; tgt = gg; }
        }
    }

    const int label = fg ? gt_labels[b * NM + tgt] : NC;
    const float4 tb = ((const float4*)gtb)[b * NM + tgt];

    o_lab[idx] = (float)label;
    ((float4*)o_box)[idx] = tb;
    o_fg[idx] = fg ? 1.0f : 0.0f;

    if (fg) {
        // _iou_batched: clipped areas, +1e-9 in denominator
        const float4 pb = ((const float4*)pd)[(size_t)b * NA + a];
        const float iw = fmaxf(fminf(tb.z, pb.z) - fmaxf(tb.x, pb.x), 0.0f);
        const float ih = fmaxf(fminf(tb.w, pb.w) - fmaxf(tb.y, pb.y), 0.0f);
        const float ovv = iw * ih;
        const float a1 = fmaxf(tb.z - tb.x, 0.0f) * fmaxf(tb.w - tb.y, 0.0f);
        const float a2 = fmaxf(pb.z - pb.x, 0.0f) * fmaxf(pb.w - pb.y, 0.0f);
        o_scr[(size_t)idx * NC + label] = ovv / (a1 + a2 - ovv + 1e-9f);
    }
}

extern "C" void kernel_launch(void* const* d_in, const int* in_sizes, int n_in,
                              void* d_out, int out_size)
{
    const float* anc = (const float*)d_in[0];   // [8400,4]
    const int*   gtl = (const int*)  d_in[1];   // [32,32,1]
    const float* gtb = (const float*)d_in[2];   // [32,32,4]
    const float* mgt = (const float*)d_in[3];   // [32,32,1]
    const float* pd  = (const float*)d_in[4];   // [32,8400,4]

    float* out   = (float*)d_out;
    float* o_lab = out;
    float* o_box = o_lab + (size_t)BSZ * NA;
    float* o_scr = o_box + (size_t)BSZ * NA * 4;
    float* o_fg  = o_scr + (size_t)BSZ * NA * NC;

    const int NS4 = BSZ * NA * NC / 4;
    k_prep<<<(NS4 + 255) / 256, 256>>>(anc, (float4*)o_scr);
    k_pairs<<<BSZ * NM, 128>>>(anc, gtb, mgt);
    k_assign<<<(BSZ * NA + 255) / 256, 256>>>(anc, gtl, gtb, pd,
                                              o_lab, o_box, o_scr, o_fg);
}

// round 7
// speedup vs baseline: 1.4031x; 1.4031x over previous
#include <cuda_runtime.h>
#include <cuda_bf16.h>
#include <math.h>

#define NA 8400
#define BSZ 32
#define NM 32
#define NC 80
#define TOPK 9
#define CAP 64

__device__ unsigned int g_maskpos[BSZ * NA];
__device__ float2       g_ac[NA];               // anchor centers

// Zero score region (float4-coalesced), zero gt bitmask, compute centers.
__global__ __launch_bounds__(256) void k_prep(
    const float* __restrict__ anc, float4* __restrict__ scr4)
{
    const int i = blockIdx.x * blockDim.x + threadIdx.x;
    const int NS4 = BSZ * NA * NC / 4;          // 5,376,000
    if (i < NS4) scr4[i] = make_float4(0.f, 0.f, 0.f, 0.f);
    if (i < BSZ * NA / 4) ((uint4*)g_maskpos)[i] = make_uint4(0u, 0u, 0u, 0u);
    if (i < NA) {
        const float4 ab = ((const float4*)anc)[i];
        g_ac[i] = make_float2((ab.x + ab.z) * 0.5f, (ab.y + ab.w) * 0.5f);
    }
}

// One BLOCK (128 thr = 4 warps) per (b,g) pair.
// Two-pass top-9 per level: pass1 = per-lane min(d2) -> T = 9th smallest
// lane-min (top-9 superset bound); pass2 = collect keys <= T (C ~ 10-20),
// then rank-select. No per-sample insert chain.
__global__ __launch_bounds__(128) void k_pairs(
    const float* __restrict__ anc,
    const float* __restrict__ gtb,
    const float* __restrict__ mask_gt)
{
    __shared__ unsigned long long s_keys[3][36];
    __shared__ unsigned long long s_buf[4][CAP];
    __shared__ int s_cand[27];

    const int tid  = threadIdx.x;
    const int lane = tid & 31;
    const int wq   = tid >> 5;                  // 0..3

    const int p = blockIdx.x;
    const int b = p >> 5;
    const int g = p & 31;
    if (mask_gt[p] <= 0.0f) return;             // block-uniform -> barriers safe

    const float4 gt = ((const float4*)gtb)[p];
    const float gx = (gt.x + gt.z) * 0.5f;
    const float gy = (gt.y + gt.w) * 0.5f;

    const int starts[3] = {0, 6400, 8000};
    const int lens[3]   = {6400, 1600, 400};
    const float BIGC = 3.0e18f;                 // sentinel center -> d2 = inf

    for (int lvl = 0; lvl < 3; ++lvl) {
        const int start = starts[lvl], L = lens[lvl];

        // ---- Pass 1: per-lane min of squared distance (8-way batched) ----
        float mn = 3.4e38f;
        for (int base = wq * 32; base < L; base += 1024) {
            float cx[8], cy[8];
            #pragma unroll
            for (int j = 0; j < 8; ++j) {
                const int al = base + j * 128 + lane;
                float2 c = make_float2(BIGC, BIGC);
                if (al < L) c = g_ac[start + al];
                cx[j] = c.x; cy[j] = c.y;
            }
            #pragma unroll
            for (int j = 0; j < 8; ++j) {
                const float dx = gx - cx[j], dy = gy - cy[j];
                mn = fminf(mn, fmaf(dx, dx, dy * dy));
            }
        }

        // T = value extracted on the 9th round of warp-min + deactivate.
        float act = mn, T = 3.4e38f;
        #pragma unroll
        for (int r = 0; r < TOPK; ++r) {
            float m = act;
            #pragma unroll
            for (int s = 16; s > 0; s >>= 1)
                m = fminf(m, __shfl_xor_sync(0xffffffffu, m, s));
            if (act == m) act = 3.4e38f;        // >=1 lane deactivates
            T = m;
        }

        // ---- Pass 2: collect all keys with d2 <= T (warp-aggregated) ----
        int cnt = 0;
        for (int base = wq * 32; base < L; base += 1024) {
            float cx[8], cy[8]; int ai[8];
            #pragma unroll
            for (int j = 0; j < 8; ++j) {
                const int al = base + j * 128 + lane;
                ai[j] = start + al;
                float2 c = make_float2(BIGC, BIGC);
                if (al < L) c = g_ac[start + al];
                cx[j] = c.x; cy[j] = c.y;
            }
            #pragma unroll
            for (int j = 0; j < 8; ++j) {
                const float dx = gx - cx[j], dy = gy - cy[j];
                const float d2 = fmaf(dx, dx, dy * dy);
                const bool q = (d2 <= T);
                const unsigned msk = __ballot_sync(0xffffffffu, q);
                if (msk) {
                    const int pos = cnt + __popc(msk & ((1u << lane) - 1u));
                    if (q && pos < CAP)
                        s_buf[wq][pos] =
                            ((unsigned long long)__float_as_uint(d2) << 32) |
                            (unsigned int)ai[j];
                    cnt += __popc(msk);
                }
            }
        }
        __syncwarp();

        // ---- Per-warp rank-select top-9 of C buffered keys ----
        const int C = cnt < CAP ? cnt : CAP;    // C >= 9 guaranteed
        for (int bb = 0; bb < C; bb += 32) {
            const int i = bb + lane;
            if (i < C) {
                const unsigned long long my = s_buf[wq][i];
                int rank = 0;
                for (int j = 0; j < C; ++j)
                    rank += (s_buf[wq][j] < my) ? 1 : 0;
                if (rank < TOPK)
                    s_keys[lvl][wq * TOPK + rank] = my;
            }
        }
        __syncwarp();                            // s_buf reused next level
    }
    __syncthreads();

    // Warp 0: rank-select top-9 of each level's 36 keys, then tail.
    if (wq == 0) {
        for (int lvl = 0; lvl < 3; ++lvl) {
            #pragma unroll
            for (int half = 0; half < 2; ++half) {
                const int i = lane + half * 32;
                if (i < 36) {
                    const unsigned long long my = s_keys[lvl][i];
                    int rank = 0;
                    #pragma unroll
                    for (int j = 0; j < 36; ++j)
                        rank += (s_keys[lvl][j] < my) ? 1 : 0;
                    if (rank < TOPK)
                        s_cand[lvl * TOPK + rank] = (int)(unsigned int)my;
                }
            }
        }
        __syncwarp();

        // Candidate overlaps (_iou2d: unclipped areas, union eps 1e-6)
        float ov = 0.0f;
        int ca = 0;
        float4 ab = make_float4(0.f, 0.f, 0.f, 0.f);
        if (lane < 27) {
            ca = s_cand[lane];
            ab = ((const float4*)anc)[ca];
            const float area1 = (gt.z - gt.x) * (gt.w - gt.y);
            const float area2 = (ab.z - ab.x) * (ab.w - ab.y);
            const float ltx = fmaxf(gt.x, ab.x), lty = fmaxf(gt.y, ab.y);
            const float rbx = fminf(gt.z, ab.z), rby = fminf(gt.w, ab.w);
            const float ww = fmaxf(rbx - ltx, 0.0f), hh = fmaxf(rby - lty, 0.0f);
            const float o = ww * hh;
            ov = o / fmaxf(area1 + area2 - o, 1e-6f);
        }

        // mean + std(ddof=1) threshold via warp sums
        float s = (lane < 27) ? ov : 0.0f;
        #pragma unroll
        for (int sft = 16; sft > 0; sft >>= 1) s += __shfl_xor_sync(0xffffffffu, s, sft);
        const float mean = s * (1.0f / 27.0f);
        float dv = (lane < 27) ? (ov - mean) * (ov - mean) : 0.0f;
        #pragma unroll
        for (int sft = 16; sft > 0; sft >>= 1) dv += __shfl_xor_sync(0xffffffffu, dv, sft);
        const float thr = mean + sqrtf(dv * (1.0f / 26.0f));

        if (lane < 27 && ov > thr) {
            const float ax = (ab.x + ab.z) * 0.5f;
            const float ay = (ab.y + ab.w) * 0.5f;
            const float mn2 = fminf(fminf(ax - gt.x, ay - gt.y),
                                    fminf(gt.z - ax, gt.w - ay));
            if (mn2 > 1e-9f) atomicOr(&g_maskpos[b * NA + ca], 1u << g);
        }
    }
}

// One thread per (b, anchor): resolve multi-assignment, write outputs.
__global__ __launch_bounds__(256) void k_assign(
    const float* __restrict__ anc,
    const int*   __restrict__ gt_labels,
    const float* __restrict__ gtb,
    const float* __restrict__ pd,
    float* __restrict__ o_lab,
    float* __restrict__ o_box,
    float* __restrict__ o_scr,
    float* __restrict__ o_fg)
{
    const int idx = blockIdx.x * blockDim.x + threadIdx.x;
    if (idx >= BSZ * NA) return;
    const int b = idx / NA;
    const int a = idx - b * NA;

    const unsigned int m = g_maskpos[idx];
    const int cnt = __popc(m);
    int tgt = 0;
    const bool fg = (cnt > 0);

    if (cnt == 1) {
        tgt = __ffs(m) - 1;
    } else if (cnt > 1) {
        // argmax over gts of full overlaps (first-occurrence ties)
        const float4 ab = ((const float4*)anc)[a];
        const float area2 = (ab.z - ab.x) * (ab.w - ab.y);
        float best = -1.0f;
        for (int gg = 0; gg < NM; ++gg) {
            const float4 gb = ((const float4*)gtb)[b * NM + gg];
            const float area1 = (gb.z - gb.x) * (gb.w - gb.y);
            const float ltx = fmaxf(gb.x, ab.x), lty = fmaxf(gb.y, ab.y);
            const float rbx = fminf(gb.z, ab.z), rby = fminf(gb.w, ab.w);
            const float ww = fmaxf(rbx - ltx, 0.0f), hh = fmaxf(rby - lty, 0.0f);
            const float ovv = ww * hh;
            const float v = ovv / fmaxf(area1 + area2 - ovv, 1e-6f);
            if (v > best) { best = v; tgt = gg; }
        }
    }

    const int label = fg ? gt_labels[b * NM + tgt] : NC;
    const float4 tb = ((const float4*)gtb)[b * NM + tgt];

    o_lab[idx] = (float)label;
    ((float4*)o_box)[idx] = tb;
    o_fg[idx] = fg ? 1.0f : 0.0f;

    if (fg) {
        // _iou_batched: clipped areas, +1e-9 in denominator
        const float4 pb = ((const float4*)pd)[(size_t)b * NA + a];
        const float iw = fmaxf(fminf(tb.z, pb.z) - fmaxf(tb.x, pb.x), 0.0f);
        const float ih = fmaxf(fminf(tb.w, pb.w) - fmaxf(tb.y, pb.y), 0.0f);
        const float ovv = iw * ih;
        const float a1 = fmaxf(tb.z - tb.x, 0.0f) * fmaxf(tb.w - tb.y, 0.0f);
        const float a2 = fmaxf(pb.z - pb.x, 0.0f) * fmaxf(pb.w - pb.y, 0.0f);
        o_scr[(size_t)idx * NC + label] = ovv / (a1 + a2 - ovv + 1e-9f);
    }
}

extern "C" void kernel_launch(void* const* d_in, const int* in_sizes, int n_in,
                              void* d_out, int out_size)
{
    const float* anc = (const float*)d_in[0];   // [8400,4]
    const int*   gtl = (const int*)  d_in[1];   // [32,32,1]
    const float* gtb = (const float*)d_in[2];   // [32,32,4]
    const float* mgt = (const float*)d_in[3];   // [32,32,1]
    const float* pd  = (const float*)d_in[4];   // [32,8400,4]

    float* out   = (float*)d_out;
    float* o_lab = out;
    float* o_box = o_lab + (size_t)BSZ * NA;
    float* o_scr = o_box + (size_t)BSZ * NA * 4;
    float* o_fg  = o_scr + (size_t)BSZ * NA * NC;

    const int NS4 = BSZ * NA * NC / 4;
    k_prep<<<(NS4 + 255) / 256, 256>>>(anc, (float4*)o_scr);
    k_pairs<<<BSZ * NM, 128>>>(anc, gtb, mgt);
    k_assign<<<(BSZ * NA + 255) / 256, 256>>>(anc, gtl, gtb, pd,
                                              o_lab, o_box, o_scr, o_fg);
}

// round 8
// speedup vs baseline: 1.4658x; 1.0447x over previous
#include <cuda_runtime.h>
#include <cuda_bf16.h>
#include <math.h>

#define NA 8400
#define BSZ 32
#define NM 32
#define NC 80
#define TOPK 9
#define CAP 64
#define AG 64          // anchors per k_assign block

__device__ unsigned int g_maskpos[BSZ * NA];
__device__ float2       g_ac[NA];               // anchor centers

// Small prep: zero gt bitmask, compute anchor centers.
__global__ __launch_bounds__(256) void k_prep(const float* __restrict__ anc)
{
    const int i = blockIdx.x * blockDim.x + threadIdx.x;
    if (i < BSZ * NA / 4) ((uint4*)g_maskpos)[i] = make_uint4(0u, 0u, 0u, 0u);
    if (i < NA) {
        const float4 ab = ((const float4*)anc)[i];
        g_ac[i] = make_float2((ab.x + ab.z) * 0.5f, (ab.y + ab.w) * 0.5f);
    }
}

// One BLOCK (128 thr = 4 warps) per (b,g) pair.
// Two-pass top-9 per level: pass1 = per-lane min(d2) -> T = 9th smallest
// lane-min (top-9 superset bound); pass2 = collect keys <= T, rank-select.
__global__ __launch_bounds__(128) void k_pairs(
    const float* __restrict__ anc,
    const float* __restrict__ gtb,
    const float* __restrict__ mask_gt)
{
    __shared__ unsigned long long s_keys[3][36];
    __shared__ unsigned long long s_buf[4][CAP];
    __shared__ int s_cand[27];

    const int tid  = threadIdx.x;
    const int lane = tid & 31;
    const int wq   = tid >> 5;                  // 0..3

    const int p = blockIdx.x;
    const int b = p >> 5;
    const int g = p & 31;
    if (mask_gt[p] <= 0.0f) return;             // block-uniform -> barriers safe

    const float4 gt = ((const float4*)gtb)[p];
    const float gx = (gt.x + gt.z) * 0.5f;
    const float gy = (gt.y + gt.w) * 0.5f;

    const int starts[3] = {0, 6400, 8000};
    const int lens[3]   = {6400, 1600, 400};
    const float BIGC = 3.0e18f;                 // sentinel center -> d2 = inf

    for (int lvl = 0; lvl < 3; ++lvl) {
        const int start = starts[lvl], L = lens[lvl];

        // ---- Pass 1: per-lane min of squared distance (8-way batched) ----
        float mn = 3.4e38f;
        for (int base = wq * 32; base < L; base += 1024) {
            float cx[8], cy[8];
            #pragma unroll
            for (int j = 0; j < 8; ++j) {
                const int al = base + j * 128 + lane;
                float2 c = make_float2(BIGC, BIGC);
                if (al < L) c = g_ac[start + al];
                cx[j] = c.x; cy[j] = c.y;
            }
            #pragma unroll
            for (int j = 0; j < 8; ++j) {
                const float dx = gx - cx[j], dy = gy - cy[j];
                mn = fminf(mn, fmaf(dx, dx, dy * dy));
            }
        }

        // T = 9th round of warp-min + deactivate.
        float act = mn, T = 3.4e38f;
        #pragma unroll
        for (int r = 0; r < TOPK; ++r) {
            float m = act;
            #pragma unroll
            for (int s = 16; s > 0; s >>= 1)
                m = fminf(m, __shfl_xor_sync(0xffffffffu, m, s));
            if (act == m) act = 3.4e38f;
            T = m;
        }

        // ---- Pass 2: collect all keys with d2 <= T (warp-aggregated) ----
        int cnt = 0;
        for (int base = wq * 32; base < L; base += 1024) {
            float cx[8], cy[8]; int ai[8];
            #pragma unroll
            for (int j = 0; j < 8; ++j) {
                const int al = base + j * 128 + lane;
                ai[j] = start + al;
                float2 c = make_float2(BIGC, BIGC);
                if (al < L) c = g_ac[start + al];
                cx[j] = c.x; cy[j] = c.y;
            }
            #pragma unroll
            for (int j = 0; j < 8; ++j) {
                const float dx = gx - cx[j], dy = gy - cy[j];
                const float d2 = fmaf(dx, dx, dy * dy);
                const bool q = (d2 <= T);
                const unsigned msk = __ballot_sync(0xffffffffu, q);
                if (msk) {
                    const int pos = cnt + __popc(msk & ((1u << lane) - 1u));
                    if (q && pos < CAP)
                        s_buf[wq][pos] =
                            ((unsigned long long)__float_as_uint(d2) << 32) |
                            (unsigned int)ai[j];
                    cnt += __popc(msk);
                }
            }
        }
        __syncwarp();

        // ---- Per-warp rank-select top-9 of C buffered keys ----
        const int C = cnt < CAP ? cnt : CAP;    // C >= 9 guaranteed
        for (int bb = 0; bb < C; bb += 32) {
            const int i = bb + lane;
            if (i < C) {
                const unsigned long long my = s_buf[wq][i];
                int rank = 0;
                for (int j = 0; j < C; ++j)
                    rank += (s_buf[wq][j] < my) ? 1 : 0;
                if (rank < TOPK)
                    s_keys[lvl][wq * TOPK + rank] = my;
            }
        }
        __syncwarp();                            // s_buf reused next level
    }
    __syncthreads();

    // Warp 0: rank-select top-9 of each level's 36 keys, then tail.
    if (wq == 0) {
        for (int lvl = 0; lvl < 3; ++lvl) {
            #pragma unroll
            for (int half = 0; half < 2; ++half) {
                const int i = lane + half * 32;
                if (i < 36) {
                    const unsigned long long my = s_keys[lvl][i];
                    int rank = 0;
                    #pragma unroll
                    for (int j = 0; j < 36; ++j)
                        rank += (s_keys[lvl][j] < my) ? 1 : 0;
                    if (rank < TOPK)
                        s_cand[lvl * TOPK + rank] = (int)(unsigned int)my;
                }
            }
        }
        __syncwarp();

        // Candidate overlaps (_iou2d: unclipped areas, union eps 1e-6)
        float ov = 0.0f;
        int ca = 0;
        float4 ab = make_float4(0.f, 0.f, 0.f, 0.f);
        if (lane < 27) {
            ca = s_cand[lane];
            ab = ((const float4*)anc)[ca];
            const float area1 = (gt.z - gt.x) * (gt.w - gt.y);
            const float area2 = (ab.z - ab.x) * (ab.w - ab.y);
            const float ltx = fmaxf(gt.x, ab.x), lty = fmaxf(gt.y, ab.y);
            const float rbx = fminf(gt.z, ab.z), rby = fminf(gt.w, ab.w);
            const float ww = fmaxf(rbx - ltx, 0.0f), hh = fmaxf(rby - lty, 0.0f);
            const float o = ww * hh;
            ov = o / fmaxf(area1 + area2 - o, 1e-6f);
        }

        // mean + std(ddof=1) threshold via warp sums
        float s = (lane < 27) ? ov : 0.0f;
        #pragma unroll
        for (int sft = 16; sft > 0; sft >>= 1) s += __shfl_xor_sync(0xffffffffu, s, sft);
        const float mean = s * (1.0f / 27.0f);
        float dv = (lane < 27) ? (ov - mean) * (ov - mean) : 0.0f;
        #pragma unroll
        for (int sft = 16; sft > 0; sft >>= 1) dv += __shfl_xor_sync(0xffffffffu, dv, sft);
        const float thr = mean + sqrtf(dv * (1.0f / 26.0f));

        if (lane < 27 && ov > thr) {
            const float ax = (ab.x + ab.z) * 0.5f;
            const float ay = (ab.y + ab.w) * 0.5f;
            const float mn2 = fminf(fminf(ax - gt.x, ay - gt.y),
                                    fminf(gt.z - ax, gt.w - ay));
            if (mn2 > 1e-9f) atomicOr(&g_maskpos[b * NA + ca], 1u << g);
        }
    }
}

// One block per AG=64 anchors. Phase A (64 thr): assignment + small outputs.
// Phase B (256 thr): coalesced full score-row writes (zeros + one value).
__global__ __launch_bounds__(256) void k_assign(
    const float* __restrict__ anc,
    const int*   __restrict__ gt_labels,
    const float* __restrict__ gtb,
    const float* __restrict__ pd,
    float* __restrict__ o_lab,
    float* __restrict__ o_box,
    float* __restrict__ o_scr,
    float* __restrict__ o_fg)
{
    __shared__ int   s_lab[AG];
    __shared__ float s_scr[AG];

    const int base = blockIdx.x * AG;
    const int tid  = threadIdx.x;

    if (tid < AG) {
        const int idx = base + tid;
        const int b = idx / NA;
        const int a = idx - b * NA;

        const unsigned int m = g_maskpos[idx];
        const int cnt = __popc(m);
        int tgt = 0;
        const bool fg = (cnt > 0);

        if (cnt == 1) {
            tgt = __ffs(m) - 1;
        } else if (cnt > 1) {
            // argmax over gts of full overlaps (first-occurrence ties)
            const float4 ab = ((const float4*)anc)[a];
            const float area2 = (ab.z - ab.x) * (ab.w - ab.y);
            float best = -1.0f;
            for (int gg = 0; gg < NM; ++gg) {
                const float4 gb = ((const float4*)gtb)[b * NM + gg];
                const float area1 = (gb.z - gb.x) * (gb.w - gb.y);
                const float ltx = fmaxf(gb.x, ab.x), lty = fmaxf(gb.y, ab.y);
                const float rbx = fminf(gb.z, ab.z), rby = fminf(gb.w, ab.w);
                const float ww = fmaxf(rbx - ltx, 0.0f), hh = fmaxf(rby - lty, 0.0f);
                const float ovv = ww * hh;
                const float v = ovv / fmaxf(area1 + area2 - ovv, 1e-6f);
                if (v > best) { best = v; tgt = gg; }
            }
        }

        const int label = fg ? gt_labels[b * NM + tgt] : NC;
        const float4 tb = ((const float4*)gtb)[b * NM + tgt];

        o_lab[idx] = (float)label;
        ((float4*)o_box)[idx] = tb;
        o_fg[idx] = fg ? 1.0f : 0.0f;

        float score = 0.0f;
        if (fg) {
            // _iou_batched: clipped areas, +1e-9 in denominator
            const float4 pb = ((const float4*)pd)[(size_t)b * NA + a];
            const float iw = fmaxf(fminf(tb.z, pb.z) - fmaxf(tb.x, pb.x), 0.0f);
            const float ih = fmaxf(fminf(tb.w, pb.w) - fmaxf(tb.y, pb.y), 0.0f);
            const float ovv = iw * ih;
            const float a1 = fmaxf(tb.z - tb.x, 0.0f) * fmaxf(tb.w - tb.y, 0.0f);
            const float a2 = fmaxf(pb.z - pb.x, 0.0f) * fmaxf(pb.w - pb.y, 0.0f);
            score = ovv / (a1 + a2 - ovv + 1e-9f);
        }
        s_lab[tid] = fg ? label : -1;
        s_scr[tid] = score;
    }
    __syncthreads();

    // Phase B: 64 rows x 20 float4 = 1280 float4s, coalesced.
    float4* sc4 = (float4*)o_scr + (size_t)base * (NC / 4);
    #pragma unroll
    for (int it = 0; it < AG * (NC / 4) / 256; ++it) {
        const int j  = it * 256 + tid;
        const int an = j / (NC / 4);
        const int q  = j - an * (NC / 4);
        float4 v = make_float4(0.f, 0.f, 0.f, 0.f);
        const int l = s_lab[an];
        if (l >= 0 && (l >> 2) == q) {
            const float sc = s_scr[an];
            if ((l & 3) == 0) v.x = sc;
            else if ((l & 3) == 1) v.y = sc;
            else if ((l & 3) == 2) v.z = sc;
            else v.w = sc;
        }
        sc4[j] = v;
    }
}

extern "C" void kernel_launch(void* const* d_in, const int* in_sizes, int n_in,
                              void* d_out, int out_size)
{
    const float* anc = (const float*)d_in[0];   // [8400,4]
    const int*   gtl = (const int*)  d_in[1];   // [32,32,1]
    const float* gtb = (const float*)d_in[2];   // [32,32,4]
    const float* mgt = (const float*)d_in[3];   // [32,32,1]
    const float* pd  = (const float*)d_in[4];   // [32,8400,4]

    float* out   = (float*)d_out;
    float* o_lab = out;
    float* o_box = o_lab + (size_t)BSZ * NA;
    float* o_scr = o_box + (size_t)BSZ * NA * 4;
    float* o_fg  = o_scr + (size_t)BSZ * NA * NC;

    k_prep<<<(BSZ * NA / 4 + 255) / 256, 256>>>(anc);
    k_pairs<<<BSZ * NM, 128>>>(anc, gtb, mgt);
    k_assign<<<BSZ * NA / AG, 256>>>(anc, gtl, gtb, pd,
                                     o_lab, o_box, o_scr, o_fg);
}